// round 16
// baseline (speedup 1.0000x reference)
#include <cuda_runtime.h>
#include <cuda_fp16.h>
#include <cstdint>

#define BB 32
#define CC 16
#define UU 16
#define LL 128
#define PW (LL*LL)
#define KP 5
#define MKC 80
#define MLU 80

// C is scaled by 4096 (exact power of 2); band2T pre-divided by 4096.
#define CSCALE 4096.0f

// ------------------------------- scratch ------------------------------------
__device__ float  g_band1p[LL*60];     // band of cheb1, [p][k][12] zero-padded
__device__ float  g_band2T[25*LL];     // packed band of cheb2 /CSCALE, [j][q]
__device__ __half g_Chi[MLU*88];       // coef*CSCALE fp16 [m][kk pad 88]

// --------------------------- helpers ------------------------------
__device__ __forceinline__ void cp16(uint32_t dst, const void* src){
  asm volatile("cp.async.cg.shared.global [%0], [%1], 16;" :: "r"(dst), "l"(src));
}
__device__ __forceinline__ void cp_commit(){ asm volatile("cp.async.commit_group;"); }
template<int N> __device__ __forceinline__ void cp_wait(){
  asm volatile("cp.async.wait_group %0;" :: "n"(N));
}
__device__ __forceinline__ uint32_t smem_u32(const void* p){
  return (uint32_t)__cvta_generic_to_shared(p);
}
// pack two floats to fp16x2 (lo arg in low half)
__device__ __forceinline__ uint32_t f2h2(float lo, float hi){
  uint32_t r;
  asm("cvt.rn.f16x2.f32 %0, %1, %2;" : "=r"(r) : "f"(hi), "f"(lo));
  return r;
}
// m16n8k16 fp16 MMA, fp32 accumulate
__device__ __forceinline__ void mma16816h(float* d, const uint32_t* a, const uint32_t* b){
  asm volatile("mma.sync.aligned.m16n8k16.row.col.f32.f16.f16.f32 "
    "{%0,%1,%2,%3}, {%4,%5,%6,%7}, {%8,%9}, {%0,%1,%2,%3};"
    : "+f"(d[0]),"+f"(d[1]),"+f"(d[2]),"+f"(d[3])
    : "r"(a[0]),"r"(a[1]),"r"(a[2]),"r"(a[3]), "r"(b[0]),"r"(b[1]));
}
__device__ __forceinline__ void ldsm4(uint32_t* r, uint32_t addr){
  asm volatile("ldmatrix.sync.aligned.m8n8.x4.shared.b16 {%0,%1,%2,%3}, [%4];"
    : "=r"(r[0]),"=r"(r[1]),"=r"(r[2]),"=r"(r[3]) : "r"(addr));
}
__device__ __forceinline__ void ldsm4t(uint32_t* r, uint32_t addr){
  asm volatile("ldmatrix.sync.aligned.m8n8.x4.trans.shared.b16 {%0,%1,%2,%3}, [%4];"
    : "=r"(r[0]),"=r"(r[1]),"=r"(r[2]),"=r"(r[3]) : "r"(addr));
}

// ============================================================================
// Prep: band tables (T_k has bandwidth k — exact structural zeros).
// band1p[p][k][j] = c1[k][p+j-k][p] for j<=2k (0 padded, 0 outside image)
// band2T[(k*k+k+d)][q] = c2[k][q+d][q]/CSCALE
// C[m=(l,u)][kk=(k1,c)]*CSCALE -> fp16, kk padded to 88.
// ============================================================================
__global__ void prep_tabs(const float* __restrict__ c1, const float* __restrict__ c2,
                          const float* __restrict__ coefs){
  int gt = blockIdx.x*128 + threadIdx.x;   // 64 x 128 = 8192
  if (gt < LL){
    int t = gt;
#pragma unroll
    for (int k = 0; k < KP; k++){
      for (int j = 0; j < 12; j++){
        float v = 0.f;
        if (j <= 2*k){
          int h = t + j - k;
          if (h >= 0 && h < LL) v = c1[(k*LL + h)*LL + t];
        }
        g_band1p[t*60 + k*12 + j] = v;
      }
      for (int d = -k; d <= k; d++){
        int h = t + d;
        bool ok = (h >= 0 && h < LL);
        g_band2T[(k*k + k + d)*LL + t] = ok ? (c2[(k*LL + h)*LL + t] * (1.0f/CSCALE)) : 0.f;
      }
    }
  }
  for (int i = gt; i < MLU*88; i += 8192){
    int m = i / 88, kk = i % 88;
    float v = 0.f;
    if (kk < MKC){
      int l = m >> 4, u = m & 15, k1 = kk >> 4, c = kk & 15;
      v = coefs[((k1*KP + l)*CC + c)*UU + u] * CSCALE;
    }
    g_Chi[i] = __float2half_rn(v);
  }
}

// ============================================================================
// Fully fused kernel, one block per (b, p):
//   phase A (fp32 stencil, k-outer, vector coefs): t1[kk][w] -> fp16 ldsm tile
//   phase B (HMMA fp16): s[m][w] = Chi[m][kk] * t1f16[kk][w]
//   phase C (trimmed-shfl f32 stencil, 4 warps x 4u): out = sum_{l,d} band2T*s
// SMEM layout (55104 B, occ 3):
//   band2T[25][128]f | t1[80][136]h | Chi[80][88]h | band1p[60]f
//   phase C overlay: s[80][132]f32 at F_SD over dead t1/C regions.
// ============================================================================
#define F_B2   0                 // band2T, 12800 B — live whole kernel
#define F_T1   12800             // t1 fp16 tile, 21760 B
#define F_CH   34560             // C fp16 tile, 14080 B
#define F_BND1 48640             // band1p, 240 B
#define F_SMEM 55104             // bytes (s overlay high-water: 12816+42240=55056)
#define F_SD   12816             // s tile [80][132] f32, overlays t1/C/band1

__global__ __launch_bounds__(320,3) void fused_all(const float* __restrict__ x,
                                                   float* __restrict__ out){
  extern __shared__ char smem[];
  uint32_t sb = smem_u32(smem);
  int tid = threadIdx.x, wid = tid >> 5, lane = tid & 31;
  int p = blockIdx.x, b = blockIdx.y;

  // ---- prologue async loads: C tile (880 chunks) + band2T (800 chunks) ----
  for (int i = tid; i < 880; i += 320){
    int r = i / 11, ch = i % 11;
    cp16(sb + F_CH + r*176 + ch*16, g_Chi + r*88 + ch*8);
  }
  for (int i = tid; i < 800; i += 320)
    cp16(sb + F_B2 + i*16, g_band2T + i*4);
  cp_commit();

  // ---- band1p[p] into smem (vector broadcast table for phase A) ----
  float* bnd_s = (float*)(smem + F_BND1);
  if (tid < 60) bnd_s[tid] = g_band1p[p*60 + tid];
  __syncthreads();

  // ---- phase A: stage-1 stencil, k-outer; coefs via broadcast LDS.128 ----
  for (int i = tid; i < 512; i += 320){
    int c  = i >> 5;
    int w4 = (i & 31) << 2;
    const float* xs = x + (size_t)(b*CC + c)*PW + w4;
    float4 win[9];
#pragma unroll
    for (int r = 0; r < 9; r++){
      int h = p - 4 + r;
      h = h < 0 ? 0 : (h > 127 ? 127 : h);
      win[r] = *(const float4*)(xs + h*LL);
    }
#pragma unroll
    for (int k = 0; k < KP; k++){
      // load ceil((2k+1)/4) coef float4s (zero padded)
      const int nv = (2*k + 4) / 4;   // 1,1,2,2,3
      float4 cfv[3];
#pragma unroll
      for (int v4 = 0; v4 < nv; v4++)
        cfv[v4] = *(const float4*)(bnd_s + k*12 + v4*4);
      float4 o = make_float4(0.f, 0.f, 0.f, 0.f);
#pragma unroll
      for (int j = 0; j <= 2*k; j++){
        float cf = ((const float*)&cfv[j >> 2])[j & 3];
        float4 v = win[4 - k + j];
        o.x = fmaf(cf, v.x, o.x);
        o.y = fmaf(cf, v.y, o.y);
        o.z = fmaf(cf, v.z, o.z);
        o.w = fmaf(cf, v.w, o.w);
      }
      uint2 hv = make_uint2(f2h2(o.x, o.y), f2h2(o.z, o.w));
      *(uint2*)(smem + F_T1 + (uint32_t)((k*CC + c)*272 + w4*2)) = hv;
    }
  }

  cp_wait<0>();
  __syncthreads();

  // ---- phase B: HMMA fp16 single-product, 10 warps = 5m x 2n,
  //      warp tile 16m x 64w
  int mi = wid >> 1, ni = wid & 1;
  float acc[8][4];
#pragma unroll
  for (int nt = 0; nt < 8; nt++)
#pragma unroll
    for (int j = 0; j < 4; j++) acc[nt][j] = 0.f;

  uint32_t arow = (uint32_t)(mi*16 + (lane & 15));
  uint32_t alh  = (uint32_t)((lane >> 4) * 16);
  uint32_t brow16 = (uint32_t)(lane & 15);
  uint32_t blh  = (uint32_t)((lane >> 4) * 16);

#pragma unroll
  for (int kt = 0; kt < 5; kt++){
    uint32_t a_h[4];
    ldsm4(a_h, sb + F_CH + arow*176 + (uint32_t)kt*32 + alh);
#pragma unroll
    for (int g = 0; g < 4; g++){
      uint32_t b_f[4];
      uint32_t baddr = ((uint32_t)kt*16 + brow16)*272 + (uint32_t)(ni*128 + g*32) + blh;
      ldsm4t(b_f, sb + F_T1 + baddr);
      mma16816h(acc[g*2+0], a_h, b_f + 0);
      mma16816h(acc[g*2+1], a_h, b_f + 2);
    }
  }

  __syncthreads();   // t1 + C tiles fully consumed; s overlay becomes legal

  // accumulators -> s tile [80][132] f32 (float2 stores)
  {
    float* sT = (float*)(smem + F_SD);
    int gid = lane >> 2, qc = (lane & 3)*2;
    int row = mi*16 + gid;
#pragma unroll
    for (int nt = 0; nt < 8; nt++){
      int col = ni*64 + nt*8 + qc;
      *(float2*)(sT + row*132 + col)     = make_float2(acc[nt][0], acc[nt][1]);
      *(float2*)(sT + (row+8)*132 + col) = make_float2(acc[nt][2], acc[nt][3]);
    }
  }
  __syncthreads();

  // ---- phase C: stage-3 stencil; warps 0-3 (one per SMSP), 4 u each.
  // Exact shfl trimming: l needs only taps [4-l, 7+l], so shfl exactly the
  // 2l edge floats per (l,u). Lanes 0/31 edge garbage x zero coefficients.
  if (wid < 4){
    const float* bT = (const float*)(smem + F_B2);    // [25][128]
    const float* sT = (const float*)(smem + F_SD);    // [80][132]
    int q4 = lane*4;
    float o[4][4];
#pragma unroll
    for (int s2 = 0; s2 < 4; s2++)
#pragma unroll
      for (int j = 0; j < 4; j++) o[s2][j] = 0.f;

#pragma unroll
    for (int l = 0; l < KP; l++){
      const int nd = 2*l + 1;
      float4 cj[9];
#pragma unroll
      for (int dd = 0; dd < nd; dd++)
        cj[dd] = *(const float4*)(bT + (l*l + dd)*LL + q4);
#pragma unroll
      for (int s2 = 0; s2 < 4; s2++){
        int u = wid + s2*4;
        const float* srow = sT + (l*UU + u)*132;
        float4 v = *(const float4*)(srow + q4);
        float w[12];
        w[4] = v.x; w[5] = v.y; w[6] = v.z; w[7] = v.w;
        if (l >= 1){
          w[3] = __shfl_up_sync(0xffffffffu, v.w, 1);
          w[8] = __shfl_down_sync(0xffffffffu, v.x, 1);
        }
        if (l >= 2){
          w[2] = __shfl_up_sync(0xffffffffu, v.z, 1);
          w[9] = __shfl_down_sync(0xffffffffu, v.y, 1);
        }
        if (l >= 3){
          w[1]  = __shfl_up_sync(0xffffffffu, v.y, 1);
          w[10] = __shfl_down_sync(0xffffffffu, v.z, 1);
        }
        if (l >= 4){
          w[0]  = __shfl_up_sync(0xffffffffu, v.x, 1);
          w[11] = __shfl_down_sync(0xffffffffu, v.w, 1);
        }
#pragma unroll
        for (int j = 0; j < 4; j++)
#pragma unroll
          for (int dd = 0; dd < nd; dd++)
            o[s2][j] = fmaf(((const float*)&cj[dd])[j], w[4 + j + dd - l], o[s2][j]);
      }
    }
#pragma unroll
    for (int s2 = 0; s2 < 4; s2++){
      int u = wid + s2*4;
      *(float4*)(out + ((size_t)(b*UU + u)*LL + p)*LL + q4) =
          make_float4(o[s2][0], o[s2][1], o[s2][2], o[s2][3]);
    }
  }
}

// ============================================================================
extern "C" void kernel_launch(void* const* d_in, const int* in_sizes, int n_in,
                              void* d_out, int out_size)
{
  const float* x = nullptr;
  const float* coefs = nullptr;
  const float* cheb1 = nullptr;
  const float* cheb2 = nullptr;
  for (int i = 0; i < n_in; i++){
    int sz = in_sizes[i];
    const float* p = (const float*)d_in[i];
    if (sz == BB*CC*PW)            x = p;
    else if (sz == KP*KP*CC*UU)    coefs = p;
    else if (sz == KP*PW){ if (!cheb1) cheb1 = p; else cheb2 = p; }
  }
  if (!cheb2) cheb2 = cheb1;
  float* out = (float*)d_out;

  cudaFuncSetAttribute(fused_all, cudaFuncAttributeMaxDynamicSharedMemorySize, F_SMEM);

  prep_tabs<<<64, 128>>>(cheb1, cheb2, coefs);
  fused_all<<<dim3(LL, BB), 320, F_SMEM>>>(x, out);
}

// round 17
// speedup vs baseline: 1.0153x; 1.0153x over previous
#include <cuda_runtime.h>
#include <cuda_fp16.h>
#include <cstdint>

#define BB 32
#define CC 16
#define UU 16
#define LL 128
#define PW (LL*LL)
#define KP 5
#define MKC 80
#define MLU 80

// C is scaled by 4096 (exact power of 2); band2T pre-divided by 4096.
#define CSCALE 4096.0f

// ------------------------------- scratch ------------------------------------
__device__ float  g_band1[LL*25];      // packed band of cheb1 [p][25]
__device__ float  g_band2T[25*LL];     // packed band of cheb2 /CSCALE, [j][q]
__device__ __half g_Chi[MLU*88];       // coef*CSCALE fp16 [m][kk pad 88]

// --------------------------- helpers ------------------------------
__device__ __forceinline__ void cp16(uint32_t dst, const void* src){
  asm volatile("cp.async.cg.shared.global [%0], [%1], 16;" :: "r"(dst), "l"(src));
}
__device__ __forceinline__ void cp_commit(){ asm volatile("cp.async.commit_group;"); }
template<int N> __device__ __forceinline__ void cp_wait(){
  asm volatile("cp.async.wait_group %0;" :: "n"(N));
}
__device__ __forceinline__ uint32_t smem_u32(const void* p){
  return (uint32_t)__cvta_generic_to_shared(p);
}
// pack two floats to fp16x2 (lo arg in low half)
__device__ __forceinline__ uint32_t f2h2(float lo, float hi){
  uint32_t r;
  asm("cvt.rn.f16x2.f32 %0, %1, %2;" : "=r"(r) : "f"(hi), "f"(lo));
  return r;
}
// m16n8k16 fp16 MMA, fp32 accumulate
__device__ __forceinline__ void mma16816h(float* d, const uint32_t* a, const uint32_t* b){
  asm volatile("mma.sync.aligned.m16n8k16.row.col.f32.f16.f16.f32 "
    "{%0,%1,%2,%3}, {%4,%5,%6,%7}, {%8,%9}, {%0,%1,%2,%3};"
    : "+f"(d[0]),"+f"(d[1]),"+f"(d[2]),"+f"(d[3])
    : "r"(a[0]),"r"(a[1]),"r"(a[2]),"r"(a[3]), "r"(b[0]),"r"(b[1]));
}
__device__ __forceinline__ void ldsm4(uint32_t* r, uint32_t addr){
  asm volatile("ldmatrix.sync.aligned.m8n8.x4.shared.b16 {%0,%1,%2,%3}, [%4];"
    : "=r"(r[0]),"=r"(r[1]),"=r"(r[2]),"=r"(r[3]) : "r"(addr));
}
__device__ __forceinline__ void ldsm4t(uint32_t* r, uint32_t addr){
  asm volatile("ldmatrix.sync.aligned.m8n8.x4.trans.shared.b16 {%0,%1,%2,%3}, [%4];"
    : "=r"(r[0]),"=r"(r[1]),"=r"(r[2]),"=r"(r[3]) : "r"(addr));
}

// ============================================================================
// Prep: band tables (T_k has bandwidth k — exact structural zeros).
// band1[p][k*k+k+d] = c1[k][p+d][p];  band2T[(k*k+k+d)][q] = c2[k][q+d][q]/CSCALE
// C[m=(l,u)][kk=(k1,c)]*CSCALE -> fp16, kk padded to 88.
// ============================================================================
__global__ void prep_tabs(const float* __restrict__ c1, const float* __restrict__ c2,
                          const float* __restrict__ coefs){
  int gt = blockIdx.x*128 + threadIdx.x;   // 64 x 128 = 8192
  if (gt < LL){
    int t = gt;
#pragma unroll
    for (int k = 0; k < KP; k++)
      for (int d = -k; d <= k; d++){
        int h = t + d;
        bool ok = (h >= 0 && h < LL);
        g_band1[t*25 + k*k + k + d] = ok ? c1[(k*LL + h)*LL + t] : 0.f;
        g_band2T[(k*k + k + d)*LL + t] = ok ? (c2[(k*LL + h)*LL + t] * (1.0f/CSCALE)) : 0.f;
      }
  }
  for (int i = gt; i < MLU*88; i += 8192){
    int m = i / 88, kk = i % 88;
    float v = 0.f;
    if (kk < MKC){
      int l = m >> 4, u = m & 15, k1 = kk >> 4, c = kk & 15;
      v = coefs[((k1*KP + l)*CC + c)*UU + u] * CSCALE;
    }
    g_Chi[i] = __float2half_rn(v);
  }
}

// ============================================================================
// Fully fused kernel, one block per (b, p-PAIR):
//   phase A: shared 10-row x window -> t1 fp16 tiles for p0 AND p1
//   phase B: two HMMA passes (C tile loaded once), s_i -> fp16 over dead t1_i
//   phase C: 8 warps (4 per p-row), shfl-windowed f32 stencil from fp16 s
// SMEM (70656 B, occ 3):
//   band2T[25][128]f | t1p0[80][136]h | t1p1[80][136]h | Chi[80][88]h | band1[2][25]f
//   s0 overlays t1p0 after B-p0; s1 overlays t1p1 after B-p1 (both fp16).
// ============================================================================
#define F_B2   0                 // band2T, 12800 B — live whole kernel
#define F_T1A  12800             // t1(p0) fp16 tile / later s0, 21760 B
#define F_T1B  34560             // t1(p1) fp16 tile / later s1, 21760 B
#define F_CH   56320             // C fp16 tile, 14080 B
#define F_BND1 70400             // band1 for p0,p1: [2][25] f32
#define F_SMEM 70656             // bytes

__global__ __launch_bounds__(320,3) void fused_all(const float* __restrict__ x,
                                                   float* __restrict__ out){
  extern __shared__ char smem[];
  uint32_t sb = smem_u32(smem);
  int tid = threadIdx.x, wid = tid >> 5, lane = tid & 31;
  int p0 = blockIdx.x*2, b = blockIdx.y;

  // ---- prologue async loads: C tile (880 chunks) + band2T (800 chunks) ----
  for (int i = tid; i < 880; i += 320){
    int r = i / 11, ch = i % 11;
    cp16(sb + F_CH + r*176 + ch*16, g_Chi + r*88 + ch*8);
  }
  for (int i = tid; i < 800; i += 320)
    cp16(sb + F_B2 + i*16, g_band2T + i*4);
  cp_commit();

  // ---- band1 for p0 and p1 into smem ----
  float* bnd_s = (float*)(smem + F_BND1);
  if (tid < 50) bnd_s[tid] = g_band1[(p0 + tid/25)*25 + (tid % 25)];
  __syncthreads();

  // ---- phase A: stage-1 stencil, shared 10-row window, both p's ----
  for (int i = tid; i < 512; i += 320){
    int c  = i >> 5;
    int w4 = (i & 31) << 2;
    const float* xs = x + (size_t)(b*CC + c)*PW + w4;
    float4 a0[5], a1[5];
#pragma unroll
    for (int k = 0; k < KP; k++){
      a0[k] = make_float4(0.f,0.f,0.f,0.f);
      a1[k] = make_float4(0.f,0.f,0.f,0.f);
    }
#pragma unroll
    for (int dd = 0; dd < 10; dd++){
      int h = p0 - 4 + dd;
      h = h < 0 ? 0 : (h > 127 ? 127 : h);
      float4 v = *(const float4*)(xs + h*LL);
      if (dd < 9){                      // contributes to p0, d = dd-4
        int d = dd - 4, ad = d < 0 ? -d : d;
#pragma unroll
        for (int k = 0; k < KP; k++)
          if (k >= ad){
            float cf = bnd_s[k*k + k + d];
            a0[k].x = fmaf(cf, v.x, a0[k].x);
            a0[k].y = fmaf(cf, v.y, a0[k].y);
            a0[k].z = fmaf(cf, v.z, a0[k].z);
            a0[k].w = fmaf(cf, v.w, a0[k].w);
          }
      }
      if (dd >= 1){                     // contributes to p1, d = dd-5
        int d = dd - 5, ad = d < 0 ? -d : d;
#pragma unroll
        for (int k = 0; k < KP; k++)
          if (k >= ad){
            float cf = bnd_s[25 + k*k + k + d];
            a1[k].x = fmaf(cf, v.x, a1[k].x);
            a1[k].y = fmaf(cf, v.y, a1[k].y);
            a1[k].z = fmaf(cf, v.z, a1[k].z);
            a1[k].w = fmaf(cf, v.w, a1[k].w);
          }
      }
    }
#pragma unroll
    for (int k = 0; k < KP; k++){
      uint32_t off = (uint32_t)((k*CC + c)*272 + w4*2);
      *(uint2*)(smem + F_T1A + off) = make_uint2(f2h2(a0[k].x, a0[k].y), f2h2(a0[k].z, a0[k].w));
      *(uint2*)(smem + F_T1B + off) = make_uint2(f2h2(a1[k].x, a1[k].y), f2h2(a1[k].z, a1[k].w));
    }
  }

  cp_wait<0>();
  __syncthreads();

  // ---- phase B: two HMMA fp16 passes, 10 warps = 5m x 2n, 16m x 64w tiles ----
  int mi = wid >> 1, ni = wid & 1;
  uint32_t arow = (uint32_t)(mi*16 + (lane & 15));
  uint32_t alh  = (uint32_t)((lane >> 4) * 16);
  uint32_t brow16 = (uint32_t)(lane & 15);
  uint32_t blh  = (uint32_t)((lane >> 4) * 16);
  int gid = lane >> 2, qc = (lane & 3)*2;
  int erow = mi*16 + gid;

  float acc[8][4];

#pragma unroll
  for (int pass = 0; pass < 2; pass++){
    uint32_t toff = pass ? (uint32_t)F_T1B : (uint32_t)F_T1A;
#pragma unroll
    for (int nt = 0; nt < 8; nt++)
#pragma unroll
      for (int j = 0; j < 4; j++) acc[nt][j] = 0.f;

#pragma unroll
    for (int kt = 0; kt < 5; kt++){
      uint32_t a_h[4];
      ldsm4(a_h, sb + F_CH + arow*176 + (uint32_t)kt*32 + alh);
#pragma unroll
      for (int g = 0; g < 4; g++){
        uint32_t b_f[4];
        uint32_t baddr = toff + ((uint32_t)kt*16 + brow16)*272 + (uint32_t)(ni*128 + g*32) + blh;
        ldsm4t(b_f, sb + baddr);
        mma16816h(acc[g*2+0], a_h, b_f + 0);
        mma16816h(acc[g*2+1], a_h, b_f + 2);
      }
    }
    __syncthreads();   // t1(pass) fully consumed by all warps -> overlay legal
    // accumulators -> s(pass) fp16 [80][136] over dead t1(pass)
#pragma unroll
    for (int nt = 0; nt < 8; nt++){
      int col = ni*64 + nt*8 + qc;
      *(uint32_t*)(smem + toff + (uint32_t)(erow*272 + col*2))     = f2h2(acc[nt][0], acc[nt][1]);
      *(uint32_t*)(smem + toff + (uint32_t)((erow+8)*272 + col*2)) = f2h2(acc[nt][2], acc[nt][3]);
    }
  }
  __syncthreads();

  // ---- phase C: stage-3 stencil; 8 warps (wid<4 -> p0, wid 4-7 -> p1),
  // each warp 4 u (u = (wid&3) + 4*s2); s read fp16, band2T from smem,
  // edge taps via shfl of packed fp16x2 words (trimmed by l).
  if (wid < 8){
    int pp   = wid >> 2;
    uint32_t soff = pp ? (uint32_t)F_T1B : (uint32_t)F_T1A;
    int pout = p0 + pp;
    int uw   = wid & 3;
    const float* bT = (const float*)(smem + F_B2);    // [25][128]
    int q4 = lane*4;
    float o[4][4];
#pragma unroll
    for (int s2 = 0; s2 < 4; s2++)
#pragma unroll
      for (int j = 0; j < 4; j++) o[s2][j] = 0.f;

#pragma unroll
    for (int l = 0; l < KP; l++){
      const int nd = 2*l + 1;
      float4 cj[9];
#pragma unroll
      for (int dd = 0; dd < nd; dd++)
        cj[dd] = *(const float4*)(bT + (l*l + dd)*LL + q4);
#pragma unroll
      for (int s2 = 0; s2 < 4; s2++){
        int u = uw + s2*4;
        uint2 v = *(const uint2*)(smem + soff + (uint32_t)((l*UU + u)*272 + q4*2));
        float2 fv0 = __half22float2(*(const __half2*)&v.x);   // w4, w5
        float2 fv1 = __half22float2(*(const __half2*)&v.y);   // w6, w7
        float w[12];
        w[4] = fv0.x; w[5] = fv0.y; w[6] = fv1.x; w[7] = fv1.y;
        if (l >= 1){
          uint32_t eu = __shfl_up_sync(0xffffffffu, v.y, 1);   // up lane (w6,w7) = my (w2,w3)
          uint32_t ed = __shfl_down_sync(0xffffffffu, v.x, 1); // down lane (w4,w5) = my (w8,w9)
          float2 fu = __half22float2(*(const __half2*)&eu);
          float2 fd = __half22float2(*(const __half2*)&ed);
          w[2] = fu.x; w[3] = fu.y; w[8] = fd.x; w[9] = fd.y;
        }
        if (l >= 3){
          uint32_t eu = __shfl_up_sync(0xffffffffu, v.x, 1);   // up (w4,w5) = my (w0,w1)
          uint32_t ed = __shfl_down_sync(0xffffffffu, v.y, 1); // down (w6,w7) = my (w10,w11)
          float2 fu = __half22float2(*(const __half2*)&eu);
          float2 fd = __half22float2(*(const __half2*)&ed);
          w[0] = fu.x; w[1] = fu.y; w[10] = fd.x; w[11] = fd.y;
        }
#pragma unroll
        for (int j = 0; j < 4; j++)
#pragma unroll
          for (int dd = 0; dd < nd; dd++)
            o[s2][j] = fmaf(((const float*)&cj[dd])[j], w[4 + j + dd - l], o[s2][j]);
      }
    }
#pragma unroll
    for (int s2 = 0; s2 < 4; s2++){
      int u = uw + s2*4;
      *(float4*)(out + ((size_t)(b*UU + u)*LL + pout)*LL + q4) =
          make_float4(o[s2][0], o[s2][1], o[s2][2], o[s2][3]);
    }
  }
}

// ============================================================================
extern "C" void kernel_launch(void* const* d_in, const int* in_sizes, int n_in,
                              void* d_out, int out_size)
{
  const float* x = nullptr;
  const float* coefs = nullptr;
  const float* cheb1 = nullptr;
  const float* cheb2 = nullptr;
  for (int i = 0; i < n_in; i++){
    int sz = in_sizes[i];
    const float* p = (const float*)d_in[i];
    if (sz == BB*CC*PW)            x = p;
    else if (sz == KP*KP*CC*UU)    coefs = p;
    else if (sz == KP*PW){ if (!cheb1) cheb1 = p; else cheb2 = p; }
  }
  if (!cheb2) cheb2 = cheb1;
  float* out = (float*)d_out;

  cudaFuncSetAttribute(fused_all, cudaFuncAttributeMaxDynamicSharedMemorySize, F_SMEM);

  prep_tabs<<<64, 128>>>(cheb1, cheb2, coefs);
  fused_all<<<dim3(LL/2, BB), 320, F_SMEM>>>(x, out);
}